// round 8
// baseline (speedup 1.0000x reference)
#include <cuda_runtime.h>
#include <cstdint>

// Fixed problem shape: N=100000, D=64, E=3200000, degree=2.
#define FEAT_D 64
#define MAX_N 100000
#define MAX_E 3200000
#define SCAN_B 1024
#define NB_SCAN ((MAX_N + SCAN_B - 1) / SCAN_B)   // 98

// Static scratch (no allocations allowed).
__device__ int   g_cursor[MAX_N];                 // histogram counts, then scatter cursor
__device__ int   g_rowptr[MAX_N + 1];
__device__ int   g_blocksums[NB_SCAN];
__device__ int   g_srcs[MAX_E];
__device__ float g_wts[MAX_E];
__device__ __align__(16) float g_tmp[(size_t)MAX_N * FEAT_D];

// ---------------------------------------------------------------------------
// CSR build
// ---------------------------------------------------------------------------
__global__ void zero_count_kernel(int N) {
    int i = blockIdx.x * blockDim.x + threadIdx.x;
    if (i < N) g_cursor[i] = 0;
}

__global__ void hist_kernel(const int* __restrict__ ei, int E) {
    int stride = gridDim.x * blockDim.x;
    for (int e = blockIdx.x * blockDim.x + threadIdx.x; e < E; e += stride)
        atomicAdd(&g_cursor[ei[e]], 1);   // row 0 of edge_index = dst
}

// block-local exclusive scan of counts -> rowptr, block totals -> g_blocksums
__global__ void scan1_kernel(int N) {
    __shared__ int sh[SCAN_B];
    int b = blockIdx.x, t = threadIdx.x;
    int i = b * SCAN_B + t;
    int v = (i < N) ? g_cursor[i] : 0;
    sh[t] = v;
    __syncthreads();
    for (int off = 1; off < SCAN_B; off <<= 1) {
        int add = (t >= off) ? sh[t - off] : 0;
        __syncthreads();
        sh[t] += add;
        __syncthreads();
    }
    if (i < N) g_rowptr[i] = sh[t] - v;               // exclusive
    if (t == SCAN_B - 1) g_blocksums[b] = sh[t];      // block total
}

// exclusive scan of the (<=98) block sums, single block
__global__ void scan2_kernel(int nb) {
    __shared__ int sh[NB_SCAN];
    int t = threadIdx.x;
    if (t < nb) sh[t] = g_blocksums[t];
    __syncthreads();
    if (t == 0) {
        int acc = 0;
        for (int i = 0; i < nb; i++) { int v = sh[i]; sh[i] = acc; acc += v; }
    }
    __syncthreads();
    if (t < nb) g_blocksums[t] = sh[t];
}

// add block offsets, init cursor, finalize rowptr[N]
__global__ void scan3_kernel(int N, int E) {
    int i = blockIdx.x * blockDim.x + threadIdx.x;
    if (i < N) {
        int v = g_rowptr[i] + g_blocksums[i / SCAN_B];
        g_rowptr[i] = v;
        g_cursor[i] = v;
    }
    if (i == 0) g_rowptr[N] = E;
}

// permute (src, w) into dst-grouped order
__global__ void scatter_kernel(const int* __restrict__ ei,
                               const float* __restrict__ w, int E) {
    int stride = gridDim.x * blockDim.x;
    for (int e = blockIdx.x * blockDim.x + threadIdx.x; e < E; e += stride) {
        int dst = ei[e];
        int src = ei[E + e];
        int pos = atomicAdd(&g_cursor[dst], 1);
        g_srcs[pos] = src;
        g_wts[pos]  = w[e];
    }
}

// ---------------------------------------------------------------------------
// SpMM gather: one warp per output row. Lane owns float2 slice (cols 2L, 2L+1).
// out[row] = sum over incoming edges w * x[src]. No atomics, single write.
// ---------------------------------------------------------------------------
__global__ void gather_kernel(const float* __restrict__ x,
                              float* __restrict__ out, int N) {
    int warp = (blockIdx.x * blockDim.x + threadIdx.x) >> 5;
    int lane = threadIdx.x & 31;
    if (warp >= N) return;

    int beg = g_rowptr[warp];
    int end = g_rowptr[warp + 1];

    float2 acc = make_float2(0.f, 0.f);
    for (int i = beg; i < end; i += 32) {
        int j = i + lane;
        int s = 0; float ww = 0.f;
        if (j < end) { s = g_srcs[j]; ww = g_wts[j]; }
        int cnt = min(32, end - i);
        #pragma unroll 4
        for (int k = 0; k < cnt; k++) {
            int   ss = __shfl_sync(0xffffffffu, s,  k);
            float fw = __shfl_sync(0xffffffffu, ww, k);
            float2 v = __ldg((const float2*)(x + (size_t)ss * FEAT_D) + lane);
            acc.x = fmaf(fw, v.x, acc.x);
            acc.y = fmaf(fw, v.y, acc.y);
        }
    }
    ((float2*)(out + (size_t)warp * FEAT_D))[lane] = acc;
}

// ---------------------------------------------------------------------------
// launch
// ---------------------------------------------------------------------------
extern "C" void kernel_launch(void* const* d_in, const int* in_sizes, int n_in,
                              void* d_out, int out_size) {
    const float* features    = (const float*)d_in[0];  // [N, 64] f32
    const float* edge_weight = (const float*)d_in[1];  // [E] f32
    const int* edge_index    = (const int*)d_in[2];    // [2, E] int32
    // d_in[3] = degree (fixed 2)

    int N = in_sizes[0] / FEAT_D;
    int E = in_sizes[1];
    float* out = (float*)d_out;

    int nb_scan = (N + SCAN_B - 1) / SCAN_B;

    // --- CSR build (by dst) ---
    zero_count_kernel<<<(N + 255) / 256, 256>>>(N);
    hist_kernel<<<2048, 256>>>(edge_index, E);
    scan1_kernel<<<nb_scan, SCAN_B>>>(N);
    scan2_kernel<<<1, 128>>>(nb_scan);
    scan3_kernel<<<(N + 255) / 256, 256>>>(N, E);
    scatter_kernel<<<2048, 256>>>(edge_index, edge_weight, E);

    // --- two SpMM passes (gather, atomic-free) ---
    int gthreads = 256;                         // 8 warps = 8 rows per block
    int gblocks = (N + 7) / 8;
    gather_kernel<<<gblocks, gthreads>>>(features, g_tmp, N);
    gather_kernel<<<gblocks, gthreads>>>(g_tmp, out, N);
}

// round 9
// speedup vs baseline: 11.8488x; 11.8488x over previous
#include <cuda_runtime.h>
#include <cstdint>

// Fixed problem shape: N=100000, D=64, E=3200000, degree=2.
#define FEAT_D 64
#define MAX_N 100000

// Intermediate buffer for the first SpMM pass (degree == 2).
__device__ __align__(16) float g_tmp[(size_t)MAX_N * FEAT_D];

// ---------------------------------------------------------------------------
// fused zero-fill: zeros g_tmp and out in one launch
// ---------------------------------------------------------------------------
__global__ void zero_both_kernel(float4* __restrict__ out4, int n4) {
    int i = blockIdx.x * blockDim.x + threadIdx.x;
    int stride = gridDim.x * blockDim.x;
    float4 z = make_float4(0.f, 0.f, 0.f, 0.f);
    float4* t4 = (float4*)g_tmp;
    for (int j = i; j < n4; j += stride) { t4[j] = z; out4[j] = z; }
}

// ---------------------------------------------------------------------------
// SpMM scatter: acc[dst] += w * x[src]
// 512 threads/block = 32 edges/block, 16 threads per edge (one float4 each).
// Edge data (dst, src, w) staged once per block in smem to kill redundant
// broadcast LDGs (R7 profile: l1tex was the top pipe at 57%).
// edge_index int32 [2, E]: row 0 = dst, row 1 = src.
// ---------------------------------------------------------------------------
#define EPB 32              // edges per block
#define SBT 512             // block threads = EPB * 16

__device__ __forceinline__ void red_add_v4(float* p, float4 v) {
    asm volatile("red.global.add.v4.f32 [%0], {%1, %2, %3, %4};"
                 :: "l"(p), "f"(v.x), "f"(v.y), "f"(v.z), "f"(v.w)
                 : "memory");
}

template <bool PASS1>
__global__ void spmm_scatter_kernel(const float* __restrict__ x,
                                    const float* __restrict__ w,
                                    const int* __restrict__ edge_index,
                                    float* __restrict__ out,
                                    int E) {
    __shared__ int   s_dst[EPB];
    __shared__ int   s_src[EPB];
    __shared__ float s_w[EPB];

    int ebase = blockIdx.x * EPB;
    int tid = threadIdx.x;

    if (tid < EPB) {
        int e = ebase + tid;
        s_dst[tid] = (e < E) ? edge_index[e] : 0;
    } else if (tid < 2 * EPB) {
        int e = ebase + tid - EPB;
        s_src[tid - EPB] = (e < E) ? edge_index[E + e] : 0;
    } else if (tid < 3 * EPB) {
        int e = ebase + tid - 2 * EPB;
        s_w[tid - 2 * EPB] = (e < E) ? w[e] : 0.f;
    }
    __syncthreads();

    int g = tid >> 4;          // edge slot within block
    int t = tid & 15;          // float4 index within the 64-float row
    int e = ebase + g;
    if (e >= E) return;

    int   src = s_src[g];
    int   dst = s_dst[g];
    float wt  = s_w[g];
    if (wt == 0.f && e >= E) return;

    const float* xin = PASS1 ? x : g_tmp;
    float4 v = __ldg((const float4*)(xin + (size_t)src * FEAT_D) + t);
    v.x *= wt; v.y *= wt; v.z *= wt; v.w *= wt;

    float* dstp = (PASS1 ? g_tmp : out) + (size_t)dst * FEAT_D + (t << 2);
    red_add_v4(dstp, v);
}

// ---------------------------------------------------------------------------
// launch
// ---------------------------------------------------------------------------
extern "C" void kernel_launch(void* const* d_in, const int* in_sizes, int n_in,
                              void* d_out, int out_size) {
    const float* features    = (const float*)d_in[0];  // [N, 64] f32
    const float* edge_weight = (const float*)d_in[1];  // [E] f32
    const int* edge_index    = (const int*)d_in[2];    // [2, E] int32
    // d_in[3] = degree (fixed 2)

    int N = in_sizes[0] / FEAT_D;
    int E = in_sizes[1];
    float* out = (float*)d_out;

    int n4 = N * (FEAT_D / 4);
    int sblocks = (E + EPB - 1) / EPB;

    zero_both_kernel<<<2048, 256>>>((float4*)out, n4);
    spmm_scatter_kernel<true ><<<sblocks, SBT>>>(features, edge_weight, edge_index, out, E);
    spmm_scatter_kernel<false><<<sblocks, SBT>>>(features, edge_weight, edge_index, out, E);
}